// round 1
// baseline (speedup 1.0000x reference)
#include <cuda_runtime.h>
#include <math.h>

// Problem constants
#define BT 512      // batch
#define IC 1152     // in capsules
#define DD 8        // in dim
#define OC 10       // out capsules
#define EC 16       // out dim
#define G  2        // batches per CTA
#define T  384      // threads per CTA (12 warps)
#define NW (T/32)
#define PRS 20      // priors row stride in floats (16 data + 4 pad -> conflict-free)

// Shared memory layout (in floats)
#define SM_PRIORS 0
#define SM_LOGITS (G*IC*PRS)                 // 46080
#define SM_RED    (SM_LOGITS + G*IC)         // +2304
#define SM_BC     (SM_RED + NW*32)           // +384
#define SM_TOTALF (SM_BC + 64)
#define SMEM_BYTES (SM_TOTALF * 4)           // ~195.3 KB

// Block-wide max of one float. Uses red[0..NW) as scratch.
__device__ __forceinline__ float block_reduce_max(float v, float* red) {
    #pragma unroll
    for (int off = 16; off; off >>= 1)
        v = fmaxf(v, __shfl_down_sync(0xFFFFFFFFu, v, off));
    int w = threadIdx.x >> 5;
    if ((threadIdx.x & 31) == 0) red[w] = v;
    __syncthreads();
    if (threadIdx.x == 0) {
        float m = red[0];
        #pragma unroll
        for (int k = 1; k < NW; k++) m = fmaxf(m, red[k]);
        red[0] = m;
    }
    __syncthreads();
    float r = red[0];
    __syncthreads();   // safe scratch reuse
    return r;
}

// Block-wide sum of N floats per thread. Result lands in bc[0..N). All threads participate.
template <int N>
__device__ __forceinline__ void block_reduce_arr(float* v, float* red, float* bc) {
    #pragma unroll
    for (int off = 16; off; off >>= 1) {
        #pragma unroll
        for (int j = 0; j < N; j++)
            v[j] += __shfl_down_sync(0xFFFFFFFFu, v[j], off);
    }
    int w = threadIdx.x >> 5, lane = threadIdx.x & 31;
    if (lane == 0) {
        #pragma unroll
        for (int j = 0; j < N; j++) red[w * 32 + j] = v[j];
    }
    __syncthreads();
    if (threadIdx.x < N) {
        float s = 0.f;
        #pragma unroll
        for (int k = 0; k < NW; k++) s += red[k * 32 + threadIdx.x];
        bc[threadIdx.x] = s;
    }
    __syncthreads();
}

__global__ __launch_bounds__(T, 1)
void caps_route_kernel(const float* __restrict__ x,
                       const float* __restrict__ W,
                       float* __restrict__ out) {
    extern __shared__ float smem[];
    float* priors = smem + SM_PRIORS;   // [G][IC][PRS]
    float* logits = smem + SM_LOGITS;   // [G][IC]
    float* red    = smem + SM_RED;      // [NW][32]
    float* bc     = smem + SM_BC;       // broadcast: [0..15]=sums, [16..31]=out_prev

    const int o  = blockIdx.y;
    const int b0 = blockIdx.x * G;
    const int tid = threadIdx.x;

    // ---------------- Phase 1: priors[g][i][e] = sum_d x[b,i,d] * W[o,i,d,e] ----------------
    {
        const int eg   = tid & 3;        // which group of 4 e's
        const int isub = tid >> 2;       // 96 i slots per pass
        for (int ib = 0; ib < IC; ib += T / 4) {
            const int i = ib + isub;
            float xv[G][DD];
            float4 acc[G];
            #pragma unroll
            for (int g = 0; g < G; g++) {
                const float4* xp = reinterpret_cast<const float4*>(
                    x + ((size_t)(b0 + g) * IC + i) * DD);
                float4 x0 = xp[0], x1 = xp[1];
                xv[g][0] = x0.x; xv[g][1] = x0.y; xv[g][2] = x0.z; xv[g][3] = x0.w;
                xv[g][4] = x1.x; xv[g][5] = x1.y; xv[g][6] = x1.z; xv[g][7] = x1.w;
                acc[g] = make_float4(0.f, 0.f, 0.f, 0.f);
            }
            const float4* wp = reinterpret_cast<const float4*>(
                W + ((size_t)o * IC + i) * (DD * EC)) + eg;
            #pragma unroll
            for (int d = 0; d < DD; d++) {
                float4 w = wp[d * 4];
                #pragma unroll
                for (int g = 0; g < G; g++) {
                    acc[g].x = fmaf(xv[g][d], w.x, acc[g].x);
                    acc[g].y = fmaf(xv[g][d], w.y, acc[g].y);
                    acc[g].z = fmaf(xv[g][d], w.z, acc[g].z);
                    acc[g].w = fmaf(xv[g][d], w.w, acc[g].w);
                }
            }
            #pragma unroll
            for (int g = 0; g < G; g++)
                *reinterpret_cast<float4*>(priors + ((size_t)g * IC + i) * PRS + eg * 4) = acc[g];
        }
    }
    __syncthreads();

    // ---------------- Phase 2: routing (3 iterations) per g ----------------
    for (int g = 0; g < G; g++) {
        float* P = priors + (size_t)g * IC * PRS;
        float* L = logits + (size_t)g * IC;

        // ---- iteration 0: probs uniform -> s = mean_i priors ----
        {
            float v[16];
            #pragma unroll
            for (int j = 0; j < 16; j++) v[j] = 0.f;
            for (int i = tid; i < IC; i += T) {
                const float4* row = reinterpret_cast<const float4*>(P + (size_t)i * PRS);
                float4 r0 = row[0], r1 = row[1], r2 = row[2], r3 = row[3];
                v[0]+=r0.x; v[1]+=r0.y; v[2]+=r0.z; v[3]+=r0.w;
                v[4]+=r1.x; v[5]+=r1.y; v[6]+=r1.z; v[7]+=r1.w;
                v[8]+=r2.x; v[9]+=r2.y; v[10]+=r2.z; v[11]+=r2.w;
                v[12]+=r3.x; v[13]+=r3.y; v[14]+=r3.z; v[15]+=r3.w;
            }
            block_reduce_arr<16>(v, red, bc);
            if (tid == 0) {
                float sq = 0.f, s[16];
                #pragma unroll
                for (int e = 0; e < 16; e++) { s[e] = bc[e] * (1.f / IC); sq += s[e] * s[e]; }
                float sc = sq / ((1.f + sq) * sqrtf(sq));
                #pragma unroll
                for (int e = 0; e < 16; e++) bc[16 + e] = s[e] * sc;   // out0
            }
            __syncthreads();
        }

        // ---- iterations 1 and 2 ----
        #pragma unroll
        for (int iter = 1; iter <= 2; iter++) {
            // read previous output
            float op[16];
            #pragma unroll
            for (int e = 0; e < 16; e++) op[e] = bc[16 + e];

            // pass A: logits update + local max
            float lmax = -1e30f;
            for (int i = tid; i < IC; i += T) {
                const float4* row = reinterpret_cast<const float4*>(P + (size_t)i * PRS);
                float4 r0 = row[0], r1 = row[1], r2 = row[2], r3 = row[3];
                float dot =
                    r0.x*op[0] + r0.y*op[1] + r0.z*op[2] + r0.w*op[3] +
                    r1.x*op[4] + r1.y*op[5] + r1.z*op[6] + r1.w*op[7] +
                    r2.x*op[8] + r2.y*op[9] + r2.z*op[10] + r2.w*op[11] +
                    r3.x*op[12] + r3.y*op[13] + r3.z*op[14] + r3.w*op[15];
                float l = (iter == 1) ? dot : (L[i] + dot);
                L[i] = l;
                lmax = fmaxf(lmax, l);
            }
            float m = block_reduce_max(lmax, red);

            // pass B: exp-weighted sums
            float v[17];
            #pragma unroll
            for (int j = 0; j < 17; j++) v[j] = 0.f;
            for (int i = tid; i < IC; i += T) {
                float p = __expf(L[i] - m);
                const float4* row = reinterpret_cast<const float4*>(P + (size_t)i * PRS);
                float4 r0 = row[0], r1 = row[1], r2 = row[2], r3 = row[3];
                v[0]+=p*r0.x; v[1]+=p*r0.y; v[2]+=p*r0.z; v[3]+=p*r0.w;
                v[4]+=p*r1.x; v[5]+=p*r1.y; v[6]+=p*r1.z; v[7]+=p*r1.w;
                v[8]+=p*r2.x; v[9]+=p*r2.y; v[10]+=p*r2.z; v[11]+=p*r2.w;
                v[12]+=p*r3.x; v[13]+=p*r3.y; v[14]+=p*r3.z; v[15]+=p*r3.w;
                v[16]+=p;
            }
            block_reduce_arr<17>(v, red, bc);
            if (tid == 0) {
                float Z = bc[16];
                float invZ = 1.f / Z;
                float sq = 0.f, s[16];
                #pragma unroll
                for (int e = 0; e < 16; e++) { s[e] = bc[e] * invZ; sq += s[e] * s[e]; }
                float sc = sq / ((1.f + sq) * sqrtf(sq));
                #pragma unroll
                for (int e = 0; e < 16; e++) bc[16 + e] = s[e] * sc;
            }
            __syncthreads();
        }

        // write final output for this (o, b): out[o, b, 0, 0, e]
        if (tid < 16)
            out[((size_t)o * BT + (b0 + g)) * EC + tid] = bc[16 + tid];
        __syncthreads();   // bc reused by next g
    }
}

extern "C" void kernel_launch(void* const* d_in, const int* in_sizes, int n_in,
                              void* d_out, int out_size) {
    const float* x = (const float*)d_in[0];           // [512,1152,8]
    const float* W = (const float*)d_in[1];           // [10,1152,8,16]
    float* out = (float*)d_out;                       // [10,512,1,1,16]

    cudaFuncSetAttribute(caps_route_kernel,
                         cudaFuncAttributeMaxDynamicSharedMemorySize, SMEM_BYTES);

    dim3 grid(BT / G, OC);
    caps_route_kernel<<<grid, T, SMEM_BYTES>>>(x, W, out);
}

// round 2
// speedup vs baseline: 1.0597x; 1.0597x over previous
#include <cuda_runtime.h>
#include <math.h>

// Problem constants
#define BT 512      // batch
#define IC 1152     // in capsules
#define DD 8        // in dim
#define OC 10       // out capsules
#define EC 16       // out dim
#define G  2        // batches per CTA
#define T  384      // threads per CTA
#define NW 12       // warps
#define NCH 12      // W chunks
#define RPC 96      // rows per chunk (T/4)
#define CHF (RPC * 128)      // floats per chunk = 12288 (96 rows x 128 floats)

// SMEM layout (floats)
//  wbuf  [2][CHF]   = 24576
//  redv  [NW][16]   = 192
//  redz  [NW]       = 12
//  redm  [NW]       = 12
//  bc    [40]
#define SMEM_FLOATS (2*CHF + NW*16 + NW + NW + 40)
#define SMEM_BYTES  (SMEM_FLOATS * 4)

__device__ __forceinline__ void cp_async16(unsigned smem_addr, const void* gptr) {
    asm volatile("cp.async.cg.shared.global [%0], [%1], 16;\n"
                 :: "r"(smem_addr), "l"(gptr));
}

__global__ __launch_bounds__(T, 1)
void caps_route_kernel(const float* __restrict__ x,
                       const float* __restrict__ W,
                       float* __restrict__ out) {
    extern __shared__ float sm[];
    float* wbuf = sm;                 // [2][CHF]
    float* redv = sm + 2 * CHF;       // [NW][16]
    float* redz = redv + NW * 16;     // [NW]
    float* redm = redz + NW;          // [NW]
    float* bc   = redm + NW;          // [40]: 0..15 sums, 16..31 out, 36 max

    const int o   = blockIdx.y;
    const int b0  = blockIdx.x * G;
    const int tid = threadIdx.x;
    const int w    = tid >> 5;
    const int lane = tid & 31;
    const int rl   = tid >> 2;   // row-local within chunk (0..95)
    const int eg   = tid & 3;    // e-quarter

    const float* Wo = W + (size_t)o * IC * (DD * EC);

    // Register-resident priors: P[g][c*4 + j] = priors[b0+g][96c + rl][eg*4 + j]
    float P[G][NCH * 4];
    float v0[G][4];
    #pragma unroll
    for (int g = 0; g < G; ++g)
        #pragma unroll
        for (int j = 0; j < 4; ++j) v0[g][j] = 0.f;

    const unsigned wbuf_base = (unsigned)__cvta_generic_to_shared(wbuf);

    // ---------------- Phase 1: staged W chunks + priors into registers ----------------
    // issue chunk 0
    {
        const float4* src = (const float4*)(Wo);
        #pragma unroll
        for (int k = 0; k < 8; ++k) {
            int idx = tid + k * T;
            cp_async16(wbuf_base + (unsigned)idx * 16u, src + idx);
        }
        asm volatile("cp.async.commit_group;\n");
    }

    #pragma unroll
    for (int c = 0; c < NCH; ++c) {
        if (c + 1 < NCH) {
            // issue chunk c+1 into the other buffer
            const float4* src = (const float4*)(Wo + (size_t)(c + 1) * CHF);
            unsigned dbase = wbuf_base + (unsigned)((c + 1) & 1) * (CHF * 4u);
            #pragma unroll
            for (int k = 0; k < 8; ++k) {
                int idx = tid + k * T;
                cp_async16(dbase + (unsigned)idx * 16u, src + idx);
            }
            asm volatile("cp.async.commit_group;\n");
            asm volatile("cp.async.wait_group 1;\n");
        } else {
            asm volatile("cp.async.wait_group 0;\n");
        }
        __syncthreads();

        const int i = c * RPC + rl;
        float xv[G][8];
        #pragma unroll
        for (int g = 0; g < G; ++g) {
            const float4* xp = (const float4*)(x + ((size_t)(b0 + g) * IC + i) * DD);
            float4 a = xp[0], b = xp[1];
            xv[g][0] = a.x; xv[g][1] = a.y; xv[g][2] = a.z; xv[g][3] = a.w;
            xv[g][4] = b.x; xv[g][5] = b.y; xv[g][6] = b.z; xv[g][7] = b.w;
        }

        const float* wb = wbuf + (size_t)(c & 1) * CHF + rl * 128 + eg * 4;
        float4 acc0 = make_float4(0.f, 0.f, 0.f, 0.f);
        float4 acc1 = make_float4(0.f, 0.f, 0.f, 0.f);
        const int rpar = rl & 1;   // bank-split XOR on d
        #pragma unroll
        for (int d = 0; d < 8; ++d) {
            const int dd = d ^ rpar;
            float4 wv = *(const float4*)(wb + dd * 16);
            float x0 = xv[0][dd], x1 = xv[1][dd];
            acc0.x = fmaf(x0, wv.x, acc0.x); acc0.y = fmaf(x0, wv.y, acc0.y);
            acc0.z = fmaf(x0, wv.z, acc0.z); acc0.w = fmaf(x0, wv.w, acc0.w);
            acc1.x = fmaf(x1, wv.x, acc1.x); acc1.y = fmaf(x1, wv.y, acc1.y);
            acc1.z = fmaf(x1, wv.z, acc1.z); acc1.w = fmaf(x1, wv.w, acc1.w);
        }
        P[0][c*4+0] = acc0.x; P[0][c*4+1] = acc0.y; P[0][c*4+2] = acc0.z; P[0][c*4+3] = acc0.w;
        P[1][c*4+0] = acc1.x; P[1][c*4+1] = acc1.y; P[1][c*4+2] = acc1.z; P[1][c*4+3] = acc1.w;
        v0[0][0] += acc0.x; v0[0][1] += acc0.y; v0[0][2] += acc0.z; v0[0][3] += acc0.w;
        v0[1][0] += acc1.x; v0[1][1] += acc1.y; v0[1][2] += acc1.z; v0[1][3] += acc1.w;
        __syncthreads();   // protect buffer (c+1)&1 from overwrite at next issue
    }

    // ---------------- Phase 2: routing per g, all from registers ----------------
    #pragma unroll
    for (int g = 0; g < G; ++g) {
        // ---- iteration 0 (uniform probs): s = mean_i priors ----
        {
            float q0 = v0[g][0], q1 = v0[g][1], q2 = v0[g][2], q3 = v0[g][3];
            #pragma unroll
            for (int off = 16; off >= 4; off >>= 1) {
                q0 += __shfl_down_sync(0xFFFFFFFFu, q0, off);
                q1 += __shfl_down_sync(0xFFFFFFFFu, q1, off);
                q2 += __shfl_down_sync(0xFFFFFFFFu, q2, off);
                q3 += __shfl_down_sync(0xFFFFFFFFu, q3, off);
            }
            if (lane < 4) {
                redv[w * 16 + lane * 4 + 0] = q0;
                redv[w * 16 + lane * 4 + 1] = q1;
                redv[w * 16 + lane * 4 + 2] = q2;
                redv[w * 16 + lane * 4 + 3] = q3;
            }
            __syncthreads();
            if (tid < 16) {
                float s = 0.f;
                #pragma unroll
                for (int k = 0; k < NW; ++k) s += redv[k * 16 + tid];
                bc[tid] = s;
            }
            __syncthreads();
            if (tid == 0) {
                float s[16], sq = 0.f;
                const float invN = 1.f / (float)IC;
                #pragma unroll
                for (int e = 0; e < 16; ++e) { s[e] = bc[e] * invN; sq += s[e] * s[e]; }
                float sc = sq / ((1.f + sq) * sqrtf(sq));
                #pragma unroll
                for (int e = 0; e < 16; ++e) bc[16 + e] = s[e] * sc;
            }
            __syncthreads();
        }

        float larr[NCH];
        #pragma unroll
        for (int iter = 1; iter <= 2; ++iter) {
            float op0 = bc[16 + eg * 4 + 0];
            float op1 = bc[16 + eg * 4 + 1];
            float op2 = bc[16 + eg * 4 + 2];
            float op3 = bc[16 + eg * 4 + 3];

            // pass A: logit update + max (per-thread, quad-combined dots)
            float lmax = -3.0e38f;
            #pragma unroll
            for (int c = 0; c < NCH; ++c) {
                float dp = P[g][c*4+0] * op0 + P[g][c*4+1] * op1
                         + P[g][c*4+2] * op2 + P[g][c*4+3] * op3;
                dp += __shfl_xor_sync(0xFFFFFFFFu, dp, 1);
                dp += __shfl_xor_sync(0xFFFFFFFFu, dp, 2);
                float l = (iter == 1) ? dp : (larr[c] + dp);
                larr[c] = l;
                lmax = fmaxf(lmax, l);
            }
            #pragma unroll
            for (int off = 16; off >= 1; off >>= 1)
                lmax = fmaxf(lmax, __shfl_down_sync(0xFFFFFFFFu, lmax, off));
            if (lane == 0) redm[w] = lmax;
            __syncthreads();
            if (tid == 0) {
                float m = redm[0];
                #pragma unroll
                for (int k = 1; k < NW; ++k) m = fmaxf(m, redm[k]);
                bc[36] = m;
            }
            __syncthreads();
            const float m = bc[36];

            // pass B: exp-weighted sums (registers only)
            float s0 = 0.f, s1 = 0.f, s2 = 0.f, s3 = 0.f, vz = 0.f;
            #pragma unroll
            for (int c = 0; c < NCH; ++c) {
                float p = __expf(larr[c] - m);
                vz += p;
                s0 = fmaf(p, P[g][c*4+0], s0);
                s1 = fmaf(p, P[g][c*4+1], s1);
                s2 = fmaf(p, P[g][c*4+2], s2);
                s3 = fmaf(p, P[g][c*4+3], s3);
            }
            #pragma unroll
            for (int off = 16; off >= 4; off >>= 1) {
                s0 += __shfl_down_sync(0xFFFFFFFFu, s0, off);
                s1 += __shfl_down_sync(0xFFFFFFFFu, s1, off);
                s2 += __shfl_down_sync(0xFFFFFFFFu, s2, off);
                s3 += __shfl_down_sync(0xFFFFFFFFu, s3, off);
                vz += __shfl_down_sync(0xFFFFFFFFu, vz, off);
            }
            if (lane < 4) {
                redv[w * 16 + lane * 4 + 0] = s0;
                redv[w * 16 + lane * 4 + 1] = s1;
                redv[w * 16 + lane * 4 + 2] = s2;
                redv[w * 16 + lane * 4 + 3] = s3;
                if (lane == 0) redz[w] = vz;
            }
            __syncthreads();
            if (tid < 16) {
                float s = 0.f;
                #pragma unroll
                for (int k = 0; k < NW; ++k) s += redv[k * 16 + tid];
                bc[tid] = s;
            }
            __syncthreads();
            if (tid == 0) {
                float Z = 0.f;
                #pragma unroll
                for (int k = 0; k < NW; ++k) Z += redz[k];
                float invZ = 1.f / Z;
                float s[16], sq = 0.f;
                #pragma unroll
                for (int e = 0; e < 16; ++e) { s[e] = bc[e] * invZ; sq += s[e] * s[e]; }
                float sc = sq / ((1.f + sq) * sqrtf(sq));
                #pragma unroll
                for (int e = 0; e < 16; ++e) bc[16 + e] = s[e] * sc;
            }
            __syncthreads();
        }

        if (tid < 16)
            out[((size_t)o * BT + (b0 + g)) * EC + tid] = bc[16 + tid];
        __syncthreads();   // bc reused by next g
    }
}

extern "C" void kernel_launch(void* const* d_in, const int* in_sizes, int n_in,
                              void* d_out, int out_size) {
    const float* x = (const float*)d_in[0];   // [512,1152,8]
    const float* W = (const float*)d_in[1];   // [10,1152,8,16]
    float* out = (float*)d_out;               // [10,512,1,1,16]

    cudaFuncSetAttribute(caps_route_kernel,
                         cudaFuncAttributeMaxDynamicSharedMemorySize, SMEM_BYTES);

    dim3 grid(BT / G, OC);
    caps_route_kernel<<<grid, T, SMEM_BYTES>>>(x, W, out);
}

// round 3
// speedup vs baseline: 1.0602x; 1.0005x over previous
#include <cuda_runtime.h>
#include <math.h>

// Problem constants
#define BT 512      // batch
#define IC 1152     // in capsules
#define DD 8        // in dim
#define OC 10       // out capsules
#define EC 16       // out dim
#define G  2        // batches per CTA
#define T  384      // threads per CTA
#define NW 12       // warps
#define NCH 12      // W chunks
#define RPC 96      // rows per chunk (T/4)
#define CHF (RPC * 128)      // floats per chunk = 12288 (96 rows x 128 floats)

// SMEM layout (floats)
//  wbuf  [2][CHF]   = 24576
//  redv  [NW][16]   = 192
//  redz  [NW]       = 12
//  redm  [NW]       = 12
//  bc    [40]
#define SMEM_FLOATS (2*CHF + NW*16 + NW + NW + 40)
#define SMEM_BYTES  (SMEM_FLOATS * 4)

__device__ __forceinline__ void cp_async16(unsigned smem_addr, const void* gptr) {
    asm volatile("cp.async.cg.shared.global [%0], [%1], 16;\n"
                 :: "r"(smem_addr), "l"(gptr));
}

__global__ __launch_bounds__(T, 1)
void caps_route_kernel(const float* __restrict__ x,
                       const float* __restrict__ W,
                       float* __restrict__ out) {
    extern __shared__ float sm[];
    float* wbuf = sm;                 // [2][CHF]
    float* redv = sm + 2 * CHF;       // [NW][16]
    float* redz = redv + NW * 16;     // [NW]
    float* redm = redz + NW;          // [NW]
    float* bc   = redm + NW;          // [40]: 0..15 sums, 16..31 out, 36 max

    const int o   = blockIdx.y;
    const int b0  = blockIdx.x * G;
    const int tid = threadIdx.x;
    const int w    = tid >> 5;
    const int lane = tid & 31;
    const int rl   = tid >> 2;   // row-local within chunk (0..95)
    const int eg   = tid & 3;    // e-quarter

    const float* Wo = W + (size_t)o * IC * (DD * EC);

    // Register-resident priors: P[g][c*4 + j] = priors[b0+g][96c + rl][eg*4 + j]
    float P[G][NCH * 4];
    float v0[G][4];
    #pragma unroll
    for (int g = 0; g < G; ++g)
        #pragma unroll
        for (int j = 0; j < 4; ++j) v0[g][j] = 0.f;

    const unsigned wbuf_base = (unsigned)__cvta_generic_to_shared(wbuf);

    // ---------------- Phase 1: staged W chunks + priors into registers ----------------
    // issue chunk 0
    {
        const float4* src = (const float4*)(Wo);
        #pragma unroll
        for (int k = 0; k < 8; ++k) {
            int idx = tid + k * T;
            cp_async16(wbuf_base + (unsigned)idx * 16u, src + idx);
        }
        asm volatile("cp.async.commit_group;\n");
    }

    #pragma unroll
    for (int c = 0; c < NCH; ++c) {
        if (c + 1 < NCH) {
            // issue chunk c+1 into the other buffer
            const float4* src = (const float4*)(Wo + (size_t)(c + 1) * CHF);
            unsigned dbase = wbuf_base + (unsigned)((c + 1) & 1) * (CHF * 4u);
            #pragma unroll
            for (int k = 0; k < 8; ++k) {
                int idx = tid + k * T;
                cp_async16(dbase + (unsigned)idx * 16u, src + idx);
            }
            asm volatile("cp.async.commit_group;\n");
            asm volatile("cp.async.wait_group 1;\n");
        } else {
            asm volatile("cp.async.wait_group 0;\n");
        }
        __syncthreads();

        const int i = c * RPC + rl;
        float xv[G][8];
        #pragma unroll
        for (int g = 0; g < G; ++g) {
            const float4* xp = (const float4*)(x + ((size_t)(b0 + g) * IC + i) * DD);
            float4 a = xp[0], b = xp[1];
            xv[g][0] = a.x; xv[g][1] = a.y; xv[g][2] = a.z; xv[g][3] = a.w;
            xv[g][4] = b.x; xv[g][5] = b.y; xv[g][6] = b.z; xv[g][7] = b.w;
        }

        const float* wb = wbuf + (size_t)(c & 1) * CHF + rl * 128 + eg * 4;
        float4 acc0 = make_float4(0.f, 0.f, 0.f, 0.f);
        float4 acc1 = make_float4(0.f, 0.f, 0.f, 0.f);
        const int rpar = rl & 1;   // bank-split XOR on d
        #pragma unroll
        for (int d = 0; d < 8; ++d) {
            const int dd = d ^ rpar;
            float4 wv = *(const float4*)(wb + dd * 16);
            float x0 = xv[0][dd], x1 = xv[1][dd];
            acc0.x = fmaf(x0, wv.x, acc0.x); acc0.y = fmaf(x0, wv.y, acc0.y);
            acc0.z = fmaf(x0, wv.z, acc0.z); acc0.w = fmaf(x0, wv.w, acc0.w);
            acc1.x = fmaf(x1, wv.x, acc1.x); acc1.y = fmaf(x1, wv.y, acc1.y);
            acc1.z = fmaf(x1, wv.z, acc1.z); acc1.w = fmaf(x1, wv.w, acc1.w);
        }
        P[0][c*4+0] = acc0.x; P[0][c*4+1] = acc0.y; P[0][c*4+2] = acc0.z; P[0][c*4+3] = acc0.w;
        P[1][c*4+0] = acc1.x; P[1][c*4+1] = acc1.y; P[1][c*4+2] = acc1.z; P[1][c*4+3] = acc1.w;
        v0[0][0] += acc0.x; v0[0][1] += acc0.y; v0[0][2] += acc0.z; v0[0][3] += acc0.w;
        v0[1][0] += acc1.x; v0[1][1] += acc1.y; v0[1][2] += acc1.z; v0[1][3] += acc1.w;
        __syncthreads();   // protect buffer (c+1)&1 from overwrite at next issue
    }

    // ---------------- Phase 2: routing per g, all from registers ----------------
    #pragma unroll
    for (int g = 0; g < G; ++g) {
        // ---- iteration 0 (uniform probs): s = mean_i priors ----
        {
            float q0 = v0[g][0], q1 = v0[g][1], q2 = v0[g][2], q3 = v0[g][3];
            #pragma unroll
            for (int off = 16; off >= 4; off >>= 1) {
                q0 += __shfl_down_sync(0xFFFFFFFFu, q0, off);
                q1 += __shfl_down_sync(0xFFFFFFFFu, q1, off);
                q2 += __shfl_down_sync(0xFFFFFFFFu, q2, off);
                q3 += __shfl_down_sync(0xFFFFFFFFu, q3, off);
            }
            if (lane < 4) {
                redv[w * 16 + lane * 4 + 0] = q0;
                redv[w * 16 + lane * 4 + 1] = q1;
                redv[w * 16 + lane * 4 + 2] = q2;
                redv[w * 16 + lane * 4 + 3] = q3;
            }
            __syncthreads();
            if (tid < 16) {
                float s = 0.f;
                #pragma unroll
                for (int k = 0; k < NW; ++k) s += redv[k * 16 + tid];
                bc[tid] = s;
            }
            __syncthreads();
            if (tid == 0) {
                float s[16], sq = 0.f;
                const float invN = 1.f / (float)IC;
                #pragma unroll
                for (int e = 0; e < 16; ++e) { s[e] = bc[e] * invN; sq += s[e] * s[e]; }
                float sc = sq / ((1.f + sq) * sqrtf(sq));
                #pragma unroll
                for (int e = 0; e < 16; ++e) bc[16 + e] = s[e] * sc;
            }
            __syncthreads();
        }

        float larr[NCH];
        #pragma unroll
        for (int iter = 1; iter <= 2; ++iter) {
            float op0 = bc[16 + eg * 4 + 0];
            float op1 = bc[16 + eg * 4 + 1];
            float op2 = bc[16 + eg * 4 + 2];
            float op3 = bc[16 + eg * 4 + 3];

            // pass A: logit update + max (per-thread, quad-combined dots)
            float lmax = -3.0e38f;
            #pragma unroll
            for (int c = 0; c < NCH; ++c) {
                float dp = P[g][c*4+0] * op0 + P[g][c*4+1] * op1
                         + P[g][c*4+2] * op2 + P[g][c*4+3] * op3;
                dp += __shfl_xor_sync(0xFFFFFFFFu, dp, 1);
                dp += __shfl_xor_sync(0xFFFFFFFFu, dp, 2);
                float l = (iter == 1) ? dp : (larr[c] + dp);
                larr[c] = l;
                lmax = fmaxf(lmax, l);
            }
            #pragma unroll
            for (int off = 16; off >= 1; off >>= 1)
                lmax = fmaxf(lmax, __shfl_down_sync(0xFFFFFFFFu, lmax, off));
            if (lane == 0) redm[w] = lmax;
            __syncthreads();
            if (tid == 0) {
                float m = redm[0];
                #pragma unroll
                for (int k = 1; k < NW; ++k) m = fmaxf(m, redm[k]);
                bc[36] = m;
            }
            __syncthreads();
            const float m = bc[36];

            // pass B: exp-weighted sums (registers only)
            float s0 = 0.f, s1 = 0.f, s2 = 0.f, s3 = 0.f, vz = 0.f;
            #pragma unroll
            for (int c = 0; c < NCH; ++c) {
                float p = __expf(larr[c] - m);
                vz += p;
                s0 = fmaf(p, P[g][c*4+0], s0);
                s1 = fmaf(p, P[g][c*4+1], s1);
                s2 = fmaf(p, P[g][c*4+2], s2);
                s3 = fmaf(p, P[g][c*4+3], s3);
            }
            #pragma unroll
            for (int off = 16; off >= 4; off >>= 1) {
                s0 += __shfl_down_sync(0xFFFFFFFFu, s0, off);
                s1 += __shfl_down_sync(0xFFFFFFFFu, s1, off);
                s2 += __shfl_down_sync(0xFFFFFFFFu, s2, off);
                s3 += __shfl_down_sync(0xFFFFFFFFu, s3, off);
                vz += __shfl_down_sync(0xFFFFFFFFu, vz, off);
            }
            if (lane < 4) {
                redv[w * 16 + lane * 4 + 0] = s0;
                redv[w * 16 + lane * 4 + 1] = s1;
                redv[w * 16 + lane * 4 + 2] = s2;
                redv[w * 16 + lane * 4 + 3] = s3;
                if (lane == 0) redz[w] = vz;
            }
            __syncthreads();
            if (tid < 16) {
                float s = 0.f;
                #pragma unroll
                for (int k = 0; k < NW; ++k) s += redv[k * 16 + tid];
                bc[tid] = s;
            }
            __syncthreads();
            if (tid == 0) {
                float Z = 0.f;
                #pragma unroll
                for (int k = 0; k < NW; ++k) Z += redz[k];
                float invZ = 1.f / Z;
                float s[16], sq = 0.f;
                #pragma unroll
                for (int e = 0; e < 16; ++e) { s[e] = bc[e] * invZ; sq += s[e] * s[e]; }
                float sc = sq / ((1.f + sq) * sqrtf(sq));
                #pragma unroll
                for (int e = 0; e < 16; ++e) bc[16 + e] = s[e] * sc;
            }
            __syncthreads();
        }

        if (tid < 16)
            out[((size_t)o * BT + (b0 + g)) * EC + tid] = bc[16 + tid];
        __syncthreads();   // bc reused by next g
    }
}

extern "C" void kernel_launch(void* const* d_in, const int* in_sizes, int n_in,
                              void* d_out, int out_size) {
    const float* x = (const float*)d_in[0];   // [512,1152,8]
    const float* W = (const float*)d_in[1];   // [10,1152,8,16]
    float* out = (float*)d_out;               // [10,512,1,1,16]

    cudaFuncSetAttribute(caps_route_kernel,
                         cudaFuncAttributeMaxDynamicSharedMemorySize, SMEM_BYTES);

    dim3 grid(BT / G, OC);
    caps_route_kernel<<<grid, T, SMEM_BYTES>>>(x, W, out);
}

// round 4
// speedup vs baseline: 1.9399x; 1.8298x over previous
#include <cuda_runtime.h>
#include <cuda_fp16.h>
#include <math.h>

// Problem constants
#define BT 512      // batch
#define IC 1152     // in capsules
#define DD 8        // in dim
#define OC 10       // out capsules
#define EC 16       // out dim
#define G  2        // batches per CTA
#define T  384      // threads per CTA
#define NW 12       // warps
#define NCH 12      // chunks of 96 rows
#define RPC 96      // rows per chunk

// Reordered fp16 copy of W: layout [o][c][j][slot(384)][8 halves]
// where slot = rl*4+eg, j selects d-pair {2j, 2j+1}, 8 halves =
// (d=2j, e=eg*4..+3), (d=2j+1, e=eg*4..+3)
__device__ __align__(16) __half Wh[(size_t)OC * IC * DD * EC];

__global__ void prep_kernel(const float* __restrict__ W) {
    int t = blockIdx.x * blockDim.x + threadIdx.x;   // < OC*IC*16 = 184320
    int slot = t % 384;
    int r = t / 384;
    int j = r & 3; r >>= 2;
    int c = r % 12;
    int o = r / 12;
    int i = c * RPC + (slot >> 2);
    int eg = slot & 3;
    const float4* src = (const float4*)(W + ((size_t)o * IC + i) * 128);
    float4 a = src[(2 * j) * 4 + eg];       // d = 2j,   e = eg*4..+3
    float4 b = src[(2 * j + 1) * 4 + eg];   // d = 2j+1, e = eg*4..+3
    __half2 h[4];
    h[0] = __floats2half2_rn(a.x, a.y);
    h[1] = __floats2half2_rn(a.z, a.w);
    h[2] = __floats2half2_rn(b.x, b.y);
    h[3] = __floats2half2_rn(b.z, b.w);
    ((uint4*)Wh)[t] = *(uint4*)h;
}

__global__ __launch_bounds__(T)
void caps_main(const float* __restrict__ x, float* __restrict__ out) {
    __shared__ float redv[NW * 16];
    __shared__ float redz[NW];
    __shared__ float redm[NW];
    __shared__ float bc[40];   // 0..15 sums, 16..31 out, 36 max

    const int o   = blockIdx.y;
    const int b0  = blockIdx.x * G;
    const int tid = threadIdx.x;
    const int w    = tid >> 5;
    const int lane = tid & 31;
    const int rl   = tid >> 2;   // row within chunk (0..95)

    const uint4* Wo = ((const uint4*)Wh) + (size_t)o * (NCH * 4 * 384) + tid;

    // Register-resident priors: P[g][c*4+jj] = priors[b0+g][c*96+rl][eg*4+jj]
    float P[G][NCH * 4];
    float v0[G][4];
    #pragma unroll
    for (int g = 0; g < G; ++g)
        #pragma unroll
        for (int jj = 0; jj < 4; ++jj) v0[g][jj] = 0.f;

    // ---------------- Phase 1: priors straight from L2 (no smem, no barriers) ----------------
    // x row pointers as float4 (2 per row per g)
    const float4* xp0 = (const float4*)(x + ((size_t)(b0 + 0) * IC + rl) * DD);
    const float4* xp1 = (const float4*)(x + ((size_t)(b0 + 1) * IC + rl) * DD);

    uint4 wc[4];
    float4 xc[4];
    #pragma unroll
    for (int j = 0; j < 4; ++j) wc[j] = Wo[j * 384];
    xc[0] = xp0[0]; xc[1] = xp0[1];
    xc[2] = xp1[0]; xc[3] = xp1[1];

    #pragma unroll
    for (int c = 0; c < NCH; ++c) {
        uint4 wn[4];
        float4 xn[4];
        if (c + 1 < NCH) {
            #pragma unroll
            for (int j = 0; j < 4; ++j) wn[j] = Wo[((c + 1) * 4 + j) * 384];
            const float4* nxp0 = xp0 + (size_t)(c + 1) * RPC * 2;
            const float4* nxp1 = xp1 + (size_t)(c + 1) * RPC * 2;
            xn[0] = nxp0[0]; xn[1] = nxp0[1];
            xn[2] = nxp1[0]; xn[3] = nxp1[1];
        }

        float4 a0 = make_float4(0.f, 0.f, 0.f, 0.f);
        float4 a1 = make_float4(0.f, 0.f, 0.f, 0.f);
        const float xg0[8] = {xc[0].x, xc[0].y, xc[0].z, xc[0].w,
                              xc[1].x, xc[1].y, xc[1].z, xc[1].w};
        const float xg1[8] = {xc[2].x, xc[2].y, xc[2].z, xc[2].w,
                              xc[3].x, xc[3].y, xc[3].z, xc[3].w};
        #pragma unroll
        for (int j = 0; j < 4; ++j) {
            const __half2* hp = (const __half2*)&wc[j];
            float2 d0e01 = __half22float2(hp[0]);
            float2 d0e23 = __half22float2(hp[1]);
            float2 d1e01 = __half22float2(hp[2]);
            float2 d1e23 = __half22float2(hp[3]);
            float xa0 = xg0[2 * j], xb0 = xg0[2 * j + 1];
            float xa1 = xg1[2 * j], xb1 = xg1[2 * j + 1];
            a0.x = fmaf(xa0, d0e01.x, fmaf(xb0, d1e01.x, a0.x));
            a0.y = fmaf(xa0, d0e01.y, fmaf(xb0, d1e01.y, a0.y));
            a0.z = fmaf(xa0, d0e23.x, fmaf(xb0, d1e23.x, a0.z));
            a0.w = fmaf(xa0, d0e23.y, fmaf(xb0, d1e23.y, a0.w));
            a1.x = fmaf(xa1, d0e01.x, fmaf(xb1, d1e01.x, a1.x));
            a1.y = fmaf(xa1, d0e01.y, fmaf(xb1, d1e01.y, a1.y));
            a1.z = fmaf(xa1, d0e23.x, fmaf(xb1, d1e23.x, a1.z));
            a1.w = fmaf(xa1, d0e23.y, fmaf(xb1, d1e23.y, a1.w));
        }
        P[0][c*4+0] = a0.x; P[0][c*4+1] = a0.y; P[0][c*4+2] = a0.z; P[0][c*4+3] = a0.w;
        P[1][c*4+0] = a1.x; P[1][c*4+1] = a1.y; P[1][c*4+2] = a1.z; P[1][c*4+3] = a1.w;
        v0[0][0] += a0.x; v0[0][1] += a0.y; v0[0][2] += a0.z; v0[0][3] += a0.w;
        v0[1][0] += a1.x; v0[1][1] += a1.y; v0[1][2] += a1.z; v0[1][3] += a1.w;

        #pragma unroll
        for (int j = 0; j < 4; ++j) wc[j] = wn[j];
        #pragma unroll
        for (int j = 0; j < 4; ++j) xc[j] = xn[j];
    }

    // ---------------- Phase 2: routing per g, all from registers ----------------
    #pragma unroll
    for (int g = 0; g < G; ++g) {
        // ---- iteration 0 (uniform probs): s = mean_i priors ----
        {
            float q0 = v0[g][0], q1 = v0[g][1], q2 = v0[g][2], q3 = v0[g][3];
            #pragma unroll
            for (int off = 16; off >= 4; off >>= 1) {
                q0 += __shfl_down_sync(0xFFFFFFFFu, q0, off);
                q1 += __shfl_down_sync(0xFFFFFFFFu, q1, off);
                q2 += __shfl_down_sync(0xFFFFFFFFu, q2, off);
                q3 += __shfl_down_sync(0xFFFFFFFFu, q3, off);
            }
            if (lane < 4) {
                redv[w * 16 + lane * 4 + 0] = q0;
                redv[w * 16 + lane * 4 + 1] = q1;
                redv[w * 16 + lane * 4 + 2] = q2;
                redv[w * 16 + lane * 4 + 3] = q3;
            }
            __syncthreads();
            if (tid < 16) {
                float s = 0.f;
                #pragma unroll
                for (int k = 0; k < NW; ++k) s += redv[k * 16 + tid];
                bc[tid] = s;
            }
            __syncthreads();
            if (tid == 0) {
                float s[16], sq = 0.f;
                const float invN = 1.f / (float)IC;
                #pragma unroll
                for (int e = 0; e < 16; ++e) { s[e] = bc[e] * invN; sq += s[e] * s[e]; }
                float sc = sq / ((1.f + sq) * sqrtf(sq));
                #pragma unroll
                for (int e = 0; e < 16; ++e) bc[16 + e] = s[e] * sc;
            }
            __syncthreads();
        }

        float larr[NCH];
        #pragma unroll
        for (int iter = 1; iter <= 2; ++iter) {
            float op0 = bc[16 + (tid & 3) * 4 + 0];
            float op1 = bc[16 + (tid & 3) * 4 + 1];
            float op2 = bc[16 + (tid & 3) * 4 + 2];
            float op3 = bc[16 + (tid & 3) * 4 + 3];

            // pass A: logit update + max (quad-combined dots)
            float lmax = -3.0e38f;
            #pragma unroll
            for (int c = 0; c < NCH; ++c) {
                float dp = P[g][c*4+0] * op0 + P[g][c*4+1] * op1
                         + P[g][c*4+2] * op2 + P[g][c*4+3] * op3;
                dp += __shfl_xor_sync(0xFFFFFFFFu, dp, 1);
                dp += __shfl_xor_sync(0xFFFFFFFFu, dp, 2);
                float l = (iter == 1) ? dp : (larr[c] + dp);
                larr[c] = l;
                lmax = fmaxf(lmax, l);
            }
            #pragma unroll
            for (int off = 16; off >= 1; off >>= 1)
                lmax = fmaxf(lmax, __shfl_down_sync(0xFFFFFFFFu, lmax, off));
            if (lane == 0) redm[w] = lmax;
            __syncthreads();
            if (tid == 0) {
                float m = redm[0];
                #pragma unroll
                for (int k = 1; k < NW; ++k) m = fmaxf(m, redm[k]);
                bc[36] = m;
            }
            __syncthreads();
            const float m = bc[36];

            // pass B: exp-weighted sums (registers only)
            float s0 = 0.f, s1 = 0.f, s2 = 0.f, s3 = 0.f, vz = 0.f;
            #pragma unroll
            for (int c = 0; c < NCH; ++c) {
                float p = __expf(larr[c] - m);
                vz += p;
                s0 = fmaf(p, P[g][c*4+0], s0);
                s1 = fmaf(p, P[g][c*4+1], s1);
                s2 = fmaf(p, P[g][c*4+2], s2);
                s3 = fmaf(p, P[g][c*4+3], s3);
            }
            #pragma unroll
            for (int off = 16; off >= 4; off >>= 1) {
                s0 += __shfl_down_sync(0xFFFFFFFFu, s0, off);
                s1 += __shfl_down_sync(0xFFFFFFFFu, s1, off);
                s2 += __shfl_down_sync(0xFFFFFFFFu, s2, off);
                s3 += __shfl_down_sync(0xFFFFFFFFu, s3, off);
                vz += __shfl_down_sync(0xFFFFFFFFu, vz, off);
            }
            if (lane < 4) {
                redv[w * 16 + lane * 4 + 0] = s0;
                redv[w * 16 + lane * 4 + 1] = s1;
                redv[w * 16 + lane * 4 + 2] = s2;
                redv[w * 16 + lane * 4 + 3] = s3;
                if (lane == 0) redz[w] = vz;   // eg=0 lanes only -> each row counted once
            }
            __syncthreads();
            if (tid < 16) {
                float s = 0.f;
                #pragma unroll
                for (int k = 0; k < NW; ++k) s += redv[k * 16 + tid];
                bc[tid] = s;
            }
            __syncthreads();
            if (tid == 0) {
                float Z = 0.f;
                #pragma unroll
                for (int k = 0; k < NW; ++k) Z += redz[k];
                float invZ = 1.f / Z;
                float s[16], sq = 0.f;
                #pragma unroll
                for (int e = 0; e < 16; ++e) { s[e] = bc[e] * invZ; sq += s[e] * s[e]; }
                float sc = sq / ((1.f + sq) * sqrtf(sq));
                #pragma unroll
                for (int e = 0; e < 16; ++e) bc[16 + e] = s[e] * sc;
            }
            __syncthreads();
        }

        if (tid < 16)
            out[((size_t)o * BT + (b0 + g)) * EC + tid] = bc[16 + tid];
        __syncthreads();   // bc reused by next g
    }
}

extern "C" void kernel_launch(void* const* d_in, const int* in_sizes, int n_in,
                              void* d_out, int out_size) {
    const float* x = (const float*)d_in[0];   // [512,1152,8]
    const float* W = (const float*)d_in[1];   // [10,1152,8,16]
    float* out = (float*)d_out;               // [10,512,1,1,16]

    // Convert + reorder W to fp16 (184320 uint4 outputs)
    prep_kernel<<<720, 256>>>(W);

    dim3 grid(BT / G, OC);
    caps_main<<<grid, T>>>(x, out);
}

// round 5
// speedup vs baseline: 2.4023x; 1.2384x over previous
#include <cuda_runtime.h>
#include <cuda_fp16.h>
#include <math.h>

// Problem constants
#define BT 512      // batch
#define IC 1152     // in capsules
#define DD 8        // in dim
#define OC 10       // out capsules
#define EC 16       // out dim
#define G  2        // batches per CTA
#define T  384      // threads per CTA
#define NW 12       // warps
#define NCH 12      // chunks of 96 rows
#define RPC 96      // rows per chunk

typedef unsigned long long u64;

// Reordered fp16 copy of W: layout [o][c][j][slot(384)][8 halves]
// slot = rl*4+eg, j selects d-pair {2j,2j+1}, 8 halves =
// (d=2j, e=eg*4..+3), (d=2j+1, e=eg*4..+3)
__device__ __align__(16) __half Wh[(size_t)OC * IC * DD * EC];

__global__ void prep_kernel(const float* __restrict__ W) {
    int t = blockIdx.x * blockDim.x + threadIdx.x;   // < OC*IC*16 = 184320
    int slot = t % 384;
    int r = t / 384;
    int j = r & 3; r >>= 2;
    int c = r % 12;
    int o = r / 12;
    int i = c * RPC + (slot >> 2);
    int eg = slot & 3;
    const float4* src = (const float4*)(W + ((size_t)o * IC + i) * 128);
    float4 a = src[(2 * j) * 4 + eg];       // d = 2j,   e = eg*4..+3
    float4 b = src[(2 * j + 1) * 4 + eg];   // d = 2j+1, e = eg*4..+3
    __half2 h[4];
    h[0] = __floats2half2_rn(a.x, a.y);
    h[1] = __floats2half2_rn(a.z, a.w);
    h[2] = __floats2half2_rn(b.x, b.y);
    h[3] = __floats2half2_rn(b.z, b.w);
    ((uint4*)Wh)[t] = *(uint4*)h;
}

// ---- packed fp32x2 helpers (Blackwell) ----
__device__ __forceinline__ u64 pk2(float a, float b) {
    u64 r; asm("mov.b64 %0, {%1, %2};" : "=l"(r) : "f"(a), "f"(b)); return r;
}
__device__ __forceinline__ void fma2(u64& d, u64 a, u64 b) {
    asm("fma.rn.f32x2 %0, %1, %2, %3;" : "=l"(d) : "l"(a), "l"(b), "l"(d));
}
__device__ __forceinline__ float2 up2(u64 a) {
    float2 f; asm("mov.b64 {%0, %1}, %2;" : "=f"(f.x), "=f"(f.y) : "l"(a)); return f;
}

__global__ __launch_bounds__(T)
void caps_main(const float* __restrict__ x, float* __restrict__ out) {
    __shared__ float redv[2][NW][16];
    __shared__ float redz[2][NW];
    __shared__ float bc[32];    // [g*16+e] current output vector

    const int o   = blockIdx.y;
    const int b0  = blockIdx.x * G;
    const int tid = threadIdx.x;
    const int w    = tid >> 5;
    const int lane = tid & 31;
    const int rl   = tid >> 2;   // row within chunk (0..95)
    const int eg   = tid & 3;    // e-quarter

    const uint4* Wo = ((const uint4*)Wh) + (size_t)o * (NCH * 4 * 384) + tid;

    // Register-resident priors: P[g][c*4+jj] = priors[b0+g][c*96+rl][eg*4+jj]
    float P[G][NCH * 4];
    u64 V00 = 0, V01 = 0, V10 = 0, V11 = 0;   // packed v0 accumulators
    const u64 ONE2 = pk2(1.f, 1.f);

    // ---------------- Phase 1: priors straight from L2 (no smem, no barriers) ----------------
    const float4* xp0 = (const float4*)(x + ((size_t)(b0 + 0) * IC + rl) * DD);
    const float4* xp1 = (const float4*)(x + ((size_t)(b0 + 1) * IC + rl) * DD);

    uint4 wc[4];
    float4 xc[4];
    #pragma unroll
    for (int j = 0; j < 4; ++j) wc[j] = Wo[j * 384];
    xc[0] = xp0[0]; xc[1] = xp0[1];
    xc[2] = xp1[0]; xc[3] = xp1[1];

    #pragma unroll
    for (int c = 0; c < NCH; ++c) {
        uint4 wn[4];
        float4 xn[4];
        if (c + 1 < NCH) {
            #pragma unroll
            for (int j = 0; j < 4; ++j) wn[j] = Wo[((c + 1) * 4 + j) * 384];
            const float4* nxp0 = xp0 + (size_t)(c + 1) * RPC * 2;
            const float4* nxp1 = xp1 + (size_t)(c + 1) * RPC * 2;
            xn[0] = nxp0[0]; xn[1] = nxp0[1];
            xn[2] = nxp1[0]; xn[3] = nxp1[1];
        }

        const float xg0[8] = {xc[0].x, xc[0].y, xc[0].z, xc[0].w,
                              xc[1].x, xc[1].y, xc[1].z, xc[1].w};
        const float xg1[8] = {xc[2].x, xc[2].y, xc[2].z, xc[2].w,
                              xc[3].x, xc[3].y, xc[3].z, xc[3].w};

        u64 A00 = 0, A01 = 0, A10 = 0, A11 = 0;  // [g][e-pair]
        #pragma unroll
        for (int j = 0; j < 4; ++j) {
            const __half2* hp = (const __half2*)&wc[j];
            float2 w0a = __half22float2(hp[0]);   // d=2j,   e01
            float2 w0b = __half22float2(hp[1]);   // d=2j,   e23
            float2 w1a = __half22float2(hp[2]);   // d=2j+1, e01
            float2 w1b = __half22float2(hp[3]);   // d=2j+1, e23
            u64 W0a = pk2(w0a.x, w0a.y), W0b = pk2(w0b.x, w0b.y);
            u64 W1a = pk2(w1a.x, w1a.y), W1b = pk2(w1b.x, w1b.y);
            u64 X0a = pk2(xg0[2*j],   xg0[2*j]);
            u64 X0b = pk2(xg0[2*j+1], xg0[2*j+1]);
            u64 X1a = pk2(xg1[2*j],   xg1[2*j]);
            u64 X1b = pk2(xg1[2*j+1], xg1[2*j+1]);
            fma2(A00, X0a, W0a); fma2(A00, X0b, W1a);
            fma2(A01, X0a, W0b); fma2(A01, X0b, W1b);
            fma2(A10, X1a, W0a); fma2(A10, X1b, W1a);
            fma2(A11, X1a, W0b); fma2(A11, X1b, W1b);
        }
        float2 f;
        f = up2(A00); P[0][c*4+0] = f.x; P[0][c*4+1] = f.y;
        f = up2(A01); P[0][c*4+2] = f.x; P[0][c*4+3] = f.y;
        f = up2(A10); P[1][c*4+0] = f.x; P[1][c*4+1] = f.y;
        f = up2(A11); P[1][c*4+2] = f.x; P[1][c*4+3] = f.y;
        fma2(V00, A00, ONE2); fma2(V01, A01, ONE2);
        fma2(V10, A10, ONE2); fma2(V11, A11, ONE2);

        #pragma unroll
        for (int j = 0; j < 4; ++j) wc[j] = wn[j];
        #pragma unroll
        for (int j = 0; j < 4; ++j) xc[j] = xn[j];
    }

    // ---------------- Phase 2: routing, both g at once ----------------
    // ---- iteration 0 (uniform probs): s = mean_i priors ----
    {
        float q[2][4];
        float2 f;
        f = up2(V00); q[0][0] = f.x; q[0][1] = f.y;
        f = up2(V01); q[0][2] = f.x; q[0][3] = f.y;
        f = up2(V10); q[1][0] = f.x; q[1][1] = f.y;
        f = up2(V11); q[1][2] = f.x; q[1][3] = f.y;
        #pragma unroll
        for (int off = 16; off >= 4; off >>= 1)
            #pragma unroll
            for (int g = 0; g < 2; ++g)
                #pragma unroll
                for (int j = 0; j < 4; ++j)
                    q[g][j] += __shfl_down_sync(0xFFFFFFFFu, q[g][j], off);
        if (lane < 4) {
            #pragma unroll
            for (int g = 0; g < 2; ++g)
                #pragma unroll
                for (int j = 0; j < 4; ++j)
                    redv[g][w][lane * 4 + j] = q[g][j];
        }
        __syncthreads();
        if (tid < 32) {
            const int g = tid >> 4;
            float s = 0.f;
            #pragma unroll
            for (int k = 0; k < NW; ++k) s += redv[g][k][tid & 15];
            s *= (1.f / (float)IC);
            float sq = s * s;
            sq += __shfl_xor_sync(0xFFFFFFFFu, sq, 1);
            sq += __shfl_xor_sync(0xFFFFFFFFu, sq, 2);
            sq += __shfl_xor_sync(0xFFFFFFFFu, sq, 4);
            sq += __shfl_xor_sync(0xFFFFFFFFu, sq, 8);
            float sc = sqrtf(sq) / (1.f + sq);
            bc[tid] = s * sc;
        }
        __syncthreads();
    }

    // ---- iterations 1 and 2: fused logit+exp+sum (no max needed; args << 88) ----
    float larr[2][NCH];
    #pragma unroll
    for (int iter = 1; iter <= 2; ++iter) {
        float op[2][4];
        #pragma unroll
        for (int g = 0; g < 2; ++g)
            #pragma unroll
            for (int j = 0; j < 4; ++j)
                op[g][j] = bc[g * 16 + eg * 4 + j];

        float s[2][4] = {{0.f,0.f,0.f,0.f},{0.f,0.f,0.f,0.f}};
        float vz[2] = {0.f, 0.f};
        #pragma unroll
        for (int c = 0; c < NCH; ++c) {
            float dp0 = P[0][c*4+0]*op[0][0] + P[0][c*4+1]*op[0][1]
                      + P[0][c*4+2]*op[0][2] + P[0][c*4+3]*op[0][3];
            float dp1 = P[1][c*4+0]*op[1][0] + P[1][c*4+1]*op[1][1]
                      + P[1][c*4+2]*op[1][2] + P[1][c*4+3]*op[1][3];
            dp0 += __shfl_xor_sync(0xFFFFFFFFu, dp0, 1);
            dp1 += __shfl_xor_sync(0xFFFFFFFFu, dp1, 1);
            dp0 += __shfl_xor_sync(0xFFFFFFFFu, dp0, 2);
            dp1 += __shfl_xor_sync(0xFFFFFFFFu, dp1, 2);
            float l0 = (iter == 1) ? dp0 : (larr[0][c] + dp0);
            float l1 = (iter == 1) ? dp1 : (larr[1][c] + dp1);
            larr[0][c] = l0;
            larr[1][c] = l1;
            float p0 = __expf(l0);
            float p1 = __expf(l1);
            vz[0] += p0; vz[1] += p1;
            #pragma unroll
            for (int j = 0; j < 4; ++j) {
                s[0][j] = fmaf(p0, P[0][c*4+j], s[0][j]);
                s[1][j] = fmaf(p1, P[1][c*4+j], s[1][j]);
            }
        }
        #pragma unroll
        for (int off = 16; off >= 4; off >>= 1) {
            #pragma unroll
            for (int g = 0; g < 2; ++g) {
                #pragma unroll
                for (int j = 0; j < 4; ++j)
                    s[g][j] += __shfl_down_sync(0xFFFFFFFFu, s[g][j], off);
                vz[g] += __shfl_down_sync(0xFFFFFFFFu, vz[g], off);
            }
        }
        if (lane < 4) {
            #pragma unroll
            for (int g = 0; g < 2; ++g)
                #pragma unroll
                for (int j = 0; j < 4; ++j)
                    redv[g][w][lane * 4 + j] = s[g][j];
            if (lane == 0) { redz[0][w] = vz[0]; redz[1][w] = vz[1]; }
        }
        __syncthreads();
        if (tid < 32) {
            const int g = tid >> 4;
            float sv = 0.f, Z = 0.f;
            #pragma unroll
            for (int k = 0; k < NW; ++k) { sv += redv[g][k][tid & 15]; Z += redz[g][k]; }
            sv *= (1.f / Z);
            float sq = sv * sv;
            sq += __shfl_xor_sync(0xFFFFFFFFu, sq, 1);
            sq += __shfl_xor_sync(0xFFFFFFFFu, sq, 2);
            sq += __shfl_xor_sync(0xFFFFFFFFu, sq, 4);
            sq += __shfl_xor_sync(0xFFFFFFFFu, sq, 8);
            float sc = sqrtf(sq) / (1.f + sq);
            bc[tid] = sv * sc;
        }
        __syncthreads();
    }

    // final output: out[o, b0+g, 0, 0, e]
    if (tid < 32) {
        const int g = tid >> 4;
        out[((size_t)o * BT + (b0 + g)) * EC + (tid & 15)] = bc[tid];
    }
}

extern "C" void kernel_launch(void* const* d_in, const int* in_sizes, int n_in,
                              void* d_out, int out_size) {
    const float* x = (const float*)d_in[0];   // [512,1152,8]
    const float* W = (const float*)d_in[1];   // [10,1152,8,16]
    float* out = (float*)d_out;               // [10,512,1,1,16]

    // Convert + reorder W to fp16 (184320 uint4 outputs)
    prep_kernel<<<720, 256>>>(W);

    dim3 grid(BT / G, OC);
    caps_main<<<grid, T>>>(x, out);
}